// round 14
// baseline (speedup 1.0000x reference)
#include <cuda_runtime.h>
#include <cuda_fp16.h>
#include <math.h>
#include <stdint.h>

#define BATCH  2
#define SEQ    2048
#define DMODEL 1024
#define NHEAD  16
#define DHEAD  64
#define MROWS  (BATCH*SEQ)   // 4096
#define KDIM   1024

// ---------------------------------------------------------------------------
// Scratch (__device__ globals; no allocation allowed)
// ---------------------------------------------------------------------------
__device__ __half g_Xq[MROWS*DMODEL];
__device__ __half g_Xk[MROWS*DMODEL];
__device__ __half g_Xv[MROWS*DMODEL];
__device__ __half g_W0[DMODEL*DMODEL];
__device__ __half g_W1[DMODEL*DMODEL];
__device__ __half g_W2[DMODEL*DMODEL];
__device__ __half g_W3[DMODEL*DMODEL];
__device__ __half g_Qh[MROWS*DMODEL];   // head-major [b][h][s][64]
__device__ __half g_Kh[MROWS*DMODEL];
__device__ __half g_Vh[MROWS*DMODEL];
__device__ __half g_Ctx[MROWS*DMODEL];  // row-major fp16 context
__device__ unsigned char g_tileAll[16*32];   // per (qtile128, ktile64) all-nonzero flag

__device__ __forceinline__ uint32_t smem_u32(const void* p) {
    uint32_t a;
    asm("{ .reg .u64 t; cvta.to.shared.u64 t, %1; cvt.u32.u64 %0, t; }" : "=r"(a) : "l"(p));
    return a;
}

// ---------------------------------------------------------------------------
// fp32 -> fp16 convert, 4 float4 per thread, batched over blockIdx.z
// ---------------------------------------------------------------------------
__global__ void to_half(const float* __restrict__ s0, const float* __restrict__ s1,
                        const float* __restrict__ s2, const float* __restrict__ s3,
                        __half* __restrict__ d0, __half* __restrict__ d1,
                        __half* __restrict__ d2, __half* __restrict__ d3, int n4)
{
    const int z = blockIdx.z;
    const float* s = (z == 0) ? s0 : (z == 1) ? s1 : (z == 2) ? s2 : s3;
    __half*      d = (z == 0) ? d0 : (z == 1) ? d1 : (z == 2) ? d2 : d3;
    const int base = blockIdx.x * (blockDim.x * 4) + threadIdx.x;

    float4 x[4];
#pragma unroll
    for (int j = 0; j < 4; ++j) {
        const int idx = base + j * blockDim.x;
        if (idx < n4) x[j] = ((const float4*)s)[idx];
    }
#pragma unroll
    for (int j = 0; j < 4; ++j) {
        const int idx = base + j * blockDim.x;
        if (idx < n4) {
            __half2 a = __floats2half2_rn(x[j].x, x[j].y);
            __half2 b = __floats2half2_rn(x[j].z, x[j].w);
            ((uint2*)d)[idx] = make_uint2(*(uint32_t*)&a, *(uint32_t*)&b);
        }
    }
}

// ---------------------------------------------------------------------------
// mask tile reduction
// ---------------------------------------------------------------------------
__global__ void mask_tiles(const int* __restrict__ mask, unsigned char* __restrict__ flags)
{
    __shared__ int ok;
    const int t = threadIdx.x;
    if (t == 0) ok = 1;
    __syncthreads();
    const int r  = t >> 1;
    const int c0 = (t & 1) * 32;
    const int* p = mask + (size_t)(blockIdx.x * 128 + r) * SEQ + blockIdx.y * 64 + c0;
    int all = 1;
#pragma unroll
    for (int i = 0; i < 8; ++i) {
        int4 v = ((const int4*)p)[i];
        all &= (v.x != 0) & (v.y != 0) & (v.z != 0) & (v.w != 0);
    }
    if (!all) ok = 0;
    __syncthreads();
    if (t == 0) flags[blockIdx.x * 32 + blockIdx.y] = (unsigned char)ok;
}

// ---------------------------------------------------------------------------
// mma primitives (fp16)
// ---------------------------------------------------------------------------
__device__ __forceinline__ void cp16(uint32_t smem, const void* gmem) {
    asm volatile("cp.async.cg.shared.global [%0], [%1], 16;" :: "r"(smem), "l"(gmem));
}
__device__ __forceinline__ void cp_commit() { asm volatile("cp.async.commit_group;"); }
template<int N> __device__ __forceinline__ void cp_wait() {
    asm volatile("cp.async.wait_group %0;" :: "n"(N));
}
__device__ __forceinline__ void ldsm4(uint32_t* r, uint32_t addr) {
    asm volatile("ldmatrix.sync.aligned.m8n8.x4.shared.b16 {%0,%1,%2,%3}, [%4];"
        : "=r"(r[0]), "=r"(r[1]), "=r"(r[2]), "=r"(r[3]) : "r"(addr));
}
__device__ __forceinline__ void ldsm4t(uint32_t* r, uint32_t addr) {
    asm volatile("ldmatrix.sync.aligned.m8n8.x4.trans.shared.b16 {%0,%1,%2,%3}, [%4];"
        : "=r"(r[0]), "=r"(r[1]), "=r"(r[2]), "=r"(r[3]) : "r"(addr));
}
__device__ __forceinline__ void mma16816(float* d, const uint32_t* a, const uint32_t* b) {
    asm volatile(
        "mma.sync.aligned.m16n8k16.row.col.f32.f16.f16.f32 "
        "{%0,%1,%2,%3}, {%4,%5,%6,%7}, {%8,%9}, {%0,%1,%2,%3};"
        : "+f"(d[0]), "+f"(d[1]), "+f"(d[2]), "+f"(d[3])
        : "r"(a[0]), "r"(a[1]), "r"(a[2]), "r"(a[3]), "r"(b[0]), "r"(b[1]));
}
__device__ __forceinline__ uint32_t packh2(float lo, float hi) {
    uint32_t r;
    asm("cvt.rn.f16x2.f32 %0, %1, %2;" : "=r"(r) : "f"(hi), "f"(lo));
    return r;
}

// ---------------------------------------------------------------------------
// fp16 mma GEMM (unchanged from round 11)
// ---------------------------------------------------------------------------
#define CTA_M   128
#define CTA_N   128
#define CTA_K   64
#define STAGES  3
#define ASTR    72
#define TILE_ELE  (128 * ASTR)
#define STAGE_ELE (2 * TILE_ELE)
#define GEMM_SMEM (STAGES * STAGE_ELE * 2)

template<int HEADS_OUT>
__global__ __launch_bounds__(256, 2)
void gemm_fp16(const __half* __restrict__ A0, const __half* __restrict__ A1,
               const __half* __restrict__ A2,
               const __half* __restrict__ B0, const __half* __restrict__ B1,
               const __half* __restrict__ B2,
               const float* __restrict__ bias0, const float* __restrict__ bias1,
               const float* __restrict__ bias2,
               __half* __restrict__ H0, __half* __restrict__ H1,
               __half* __restrict__ H2, float* __restrict__ Y)
{
    extern __shared__ char smem[];
    const uint32_t sb = smem_u32(smem);
    const int t = threadIdx.x;
    const int warp = t >> 5, lane = t & 31;
    const int wm = warp >> 1, wn = warp & 1;
    const int row0 = blockIdx.y * CTA_M;
    const int col0 = blockIdx.x * CTA_N;
    const int z = blockIdx.z;

    const __half* A = (z == 0) ? A0 : (z == 1) ? A1 : A2;
    const __half* B = (z == 0) ? B0 : (z == 1) ? B1 : B2;
    const float* bias = (z == 0) ? bias0 : (z == 1) ? bias1 : bias2;
    __half* H = (z == 0) ? H0 : (z == 1) ? H1 : H2;

    const int NK = KDIM / CTA_K;   // 16

#pragma unroll
    for (int s = 0; s < STAGES - 1; ++s) {
        const uint32_t so = sb + s * STAGE_ELE * 2;
#pragma unroll
        for (int i = 0; i < 4; ++i) {
            const int id = i * 256 + t;
            const int row = id >> 3, seg = id & 7;
            const uint32_t sm = row * 144 + seg * 16;
            cp16(so + sm,
                 (const char*)A + ((size_t)(row0 + row) * KDIM + s * CTA_K) * 2 + seg * 16);
            cp16(so + TILE_ELE * 2 + sm,
                 (const char*)B + ((size_t)(col0 + row) * KDIM + s * CTA_K) * 2 + seg * 16);
        }
        cp_commit();
    }

    float acc[2][8][4];
#pragma unroll
    for (int i = 0; i < 2; ++i)
#pragma unroll
        for (int j = 0; j < 8; ++j)
#pragma unroll
            for (int c = 0; c < 4; ++c) acc[i][j][c] = 0.f;

    const int g = lane >> 3, r = lane & 7;
    const int aRow = wm * 32 + (g & 1) * 8 + r;
    const int aK   = (g >> 1) * 8;
    const int bRow = wn * 64 + (g >> 1) * 8 + r;
    const int bK   = (g & 1) * 8;

    for (int ks = 0; ks < NK; ++ks) {
        cp_wait<1>();
        __syncthreads();

        const int kn = ks + STAGES - 1;
        if (kn < NK) {
            const uint32_t so = sb + (kn % STAGES) * STAGE_ELE * 2;
#pragma unroll
            for (int i = 0; i < 4; ++i) {
                const int id = i * 256 + t;
                const int row = id >> 3, seg = id & 7;
                const uint32_t sm = row * 144 + seg * 16;
                cp16(so + sm,
                     (const char*)A + ((size_t)(row0 + row) * KDIM + kn * CTA_K) * 2 + seg * 16);
                cp16(so + TILE_ELE * 2 + sm,
                     (const char*)B + ((size_t)(col0 + row) * KDIM + kn * CTA_K) * 2 + seg * 16);
            }
        }
        cp_commit();

        const uint32_t sAst = sb + (ks % STAGES) * STAGE_ELE * 2;
        const uint32_t sBst = sAst + TILE_ELE * 2;

#pragma unroll
        for (int kk = 0; kk < 4; ++kk) {
            uint32_t af[2][4], bf[4][4];
#pragma unroll
            for (int mt = 0; mt < 2; ++mt)
                ldsm4(af[mt], sAst + ((aRow + mt * 16) * ASTR + kk * 16 + aK) * 2);
#pragma unroll
            for (int nn = 0; nn < 4; ++nn)
                ldsm4(bf[nn], sBst + ((bRow + nn * 16) * ASTR + kk * 16 + bK) * 2);
#pragma unroll
            for (int mt = 0; mt < 2; ++mt)
#pragma unroll
                for (int nn = 0; nn < 4; ++nn) {
                    mma16816(acc[mt][nn * 2 + 0], af[mt], &bf[nn][0]);
                    mma16816(acc[mt][nn * 2 + 1], af[mt], &bf[nn][2]);
                }
        }
    }

    const int mBase = row0 + wm * 32 + (lane >> 2);
    const int nBase = col0 + wn * 64 + (lane & 3) * 2;
#pragma unroll
    for (int mt = 0; mt < 2; ++mt) {
#pragma unroll
        for (int nt = 0; nt < 8; ++nt) {
            const int gcol = nBase + nt * 8;
            const float2 bb = *(const float2*)&bias[gcol];
            const float v0a = acc[mt][nt][0] + bb.x;
            const float v0b = acc[mt][nt][1] + bb.y;
            const float v1a = acc[mt][nt][2] + bb.x;
            const float v1b = acc[mt][nt][3] + bb.y;
            const int grow0 = mBase + mt * 16;
            const int grow1 = grow0 + 8;
            if (HEADS_OUT) {
                const int h = gcol >> 6, c = gcol & 63;
                const int b0 = grow0 >> 11, s0 = grow0 & 2047;
                const int b1 = grow1 >> 11, s1 = grow1 & 2047;
                const size_t d0 = ((size_t)(b0 * 16 + h) * 2048 + s0) * 64 + c;
                const size_t d1 = ((size_t)(b1 * 16 + h) * 2048 + s1) * 64 + c;
                __half2 p0 = __floats2half2_rn(v0a, v0b);
                __half2 p1 = __floats2half2_rn(v1a, v1b);
                *(uint32_t*)(H + d0) = *(uint32_t*)&p0;
                *(uint32_t*)(H + d1) = *(uint32_t*)&p1;
            } else {
                *(float2*)&Y[(size_t)grow0 * DMODEL + gcol] = make_float2(v0a, v0b);
                *(float2*)&Y[(size_t)grow1 * DMODEL + gcol] = make_float2(v1a, v1b);
            }
        }
    }
}

// ---------------------------------------------------------------------------
// Flash attention, fp16 HMMA: 256 threads / 8 warps, 16 Q-rows per warp.
// Q-tile 128, K-tile 64, double-buffered K/V, mask tile flags.
// smem (halves): Q[128][72] + 2 stages of (K[64][72] + V[64][72])
// ---------------------------------------------------------------------------
#define FS_STR   72
#define QELE     (128 * FS_STR)       // 9216
#define KVELE    (64 * FS_STR)        // 4608
#define FLASH_SMEM ((QELE + 4 * KVELE) * 2)   // 55296 bytes

__global__ __launch_bounds__(256, 2)
void flash_mma(const __half* __restrict__ Qg, const __half* __restrict__ Kg,
               const __half* __restrict__ Vg, const int* __restrict__ mask,
               const unsigned char* __restrict__ tileAll, __half* __restrict__ Ctx)
{
    extern __shared__ char smem[];
    const uint32_t sb = smem_u32(smem);
    const int t = threadIdx.x;
    const int warp = t >> 5, lane = t & 31;
    const int grp = lane >> 2, tg = lane & 3;
    const int bh = blockIdx.y;
    const int b  = bh >> 4, h = bh & 15;
    const int q0 = blockIdx.x * 128;

    const size_t headOff = (size_t)bh * SEQ * DHEAD;
    const __half* Qhg = Qg + headOff;
    const __half* Khg = Kg + headOff;
    const __half* Vhg = Vg + headOff;

    const int ldrow = t >> 3, ldseg = t & 7;   // 32 rows x 8 segs per pass

    // prologue: Q (4 segs/thread) + KV(0) as group0; KV(1) as group1
#pragma unroll
    for (int i = 0; i < 4; ++i) {
        const int id = i * 256 + t;
        const int row = id >> 3, seg = id & 7;
        cp16(sb + row * 144 + seg * 16,
             (const char*)Qhg + (size_t)(q0 + row) * 128 + seg * 16);
    }
#pragma unroll
    for (int i = 0; i < 2; ++i) {
        const int row = i * 32 + ldrow;
        const size_t go = (size_t)row * 128 + ldseg * 16;
        const uint32_t so = row * 144 + ldseg * 16;
        cp16(sb + QELE * 2 + so, (const char*)Khg + go);
        cp16(sb + (QELE + KVELE) * 2 + so, (const char*)Vhg + go);
    }
    cp_commit();
#pragma unroll
    for (int i = 0; i < 2; ++i) {
        const int row = i * 32 + ldrow;
        const size_t go = (size_t)(64 + row) * 128 + ldseg * 16;
        const uint32_t so = row * 144 + ldseg * 16;
        cp16(sb + (QELE + 2 * KVELE) * 2 + so, (const char*)Khg + go);
        cp16(sb + (QELE + 3 * KVELE) * 2 + so, (const char*)Vhg + go);
    }
    cp_commit();

    const int g2 = lane >> 3, r8 = lane & 7;
    const int arow = (g2 & 1) * 8 + r8;         // row within warp's 16
    const int akoff = (lane >> 4) * 8;
    const int brow = (lane >> 4) * 8 + r8;
    const int bkoff = (g2 & 1) * 8;

    float ctx[8][4];
    float mrow0 = -INFINITY, mrow1 = -INFINITY, lrow0 = 0.f, lrow1 = 0.f;
#pragma unroll
    for (int j = 0; j < 8; ++j)
#pragma unroll
        for (int c = 0; c < 4; ++c) ctx[j][c] = 0.f;

    const int qr0 = q0 + warp * 16 + grp;       // rows qr0, qr0+8
    const unsigned char* flagRow = tileAll + blockIdx.x * 32;

    for (int kt = 0; kt < SEQ / 64; ++kt) {
        const int k0 = kt * 64;
        const int st = kt & 1;
        const uint32_t sK = sb + (QELE + 2 * st * KVELE) * 2;
        const uint32_t sV = sK + KVELE * 2;

        cp_wait<1>();
        __syncthreads();

        const int allOnes = flagRow[kt];

        // ---- S = Q K^T ----
        float S[8][4];
#pragma unroll
        for (int j = 0; j < 8; ++j)
#pragma unroll
            for (int c = 0; c < 4; ++c) S[j][c] = 0.f;

#pragma unroll
        for (int kk = 0; kk < 4; ++kk) {
            uint32_t aQ[4];
            const uint32_t qa = (warp * 16 + arow) * FS_STR + kk * 16 + akoff;
            ldsm4(aQ, sb + qa * 2);
#pragma unroll
            for (int nt = 0; nt < 4; ++nt) {
                uint32_t bK4[4];
                const uint32_t ka = (nt * 16 + brow) * FS_STR + kk * 16 + bkoff;
                ldsm4(bK4, sK + ka * 2);
                mma16816(S[nt * 2 + 0], aQ, &bK4[0]);
                mma16816(S[nt * 2 + 1], aQ, &bK4[2]);
            }
        }

        // ---- mask/scale + online softmax + pack P ----
        const int row0 = qr0;
        const int row1 = qr0 + 8;
        float mx0 = -INFINITY, mx1 = -INFINITY;
        if (allOnes) {
#pragma unroll
            for (int j = 0; j < 8; ++j) {
                S[j][0] *= 0.125f; S[j][1] *= 0.125f;
                S[j][2] *= 0.125f; S[j][3] *= 0.125f;
                mx0 = fmaxf(mx0, fmaxf(S[j][0], S[j][1]));
                mx1 = fmaxf(mx1, fmaxf(S[j][2], S[j][3]));
            }
        } else {
#pragma unroll
            for (int j = 0; j < 8; ++j) {
                const int kcol = k0 + j * 8 + tg * 2;
                const int2 mv0 = *(const int2*)&mask[(size_t)row0 * SEQ + kcol];
                const int2 mv1 = *(const int2*)&mask[(size_t)row1 * SEQ + kcol];
                S[j][0] = mv0.x ? S[j][0] * 0.125f : -1e9f;
                S[j][1] = mv0.y ? S[j][1] * 0.125f : -1e9f;
                S[j][2] = mv1.x ? S[j][2] * 0.125f : -1e9f;
                S[j][3] = mv1.y ? S[j][3] * 0.125f : -1e9f;
                mx0 = fmaxf(mx0, fmaxf(S[j][0], S[j][1]));
                mx1 = fmaxf(mx1, fmaxf(S[j][2], S[j][3]));
            }
        }
        mx0 = fmaxf(mx0, __shfl_xor_sync(0xffffffffu, mx0, 1));
        mx0 = fmaxf(mx0, __shfl_xor_sync(0xffffffffu, mx0, 2));
        mx1 = fmaxf(mx1, __shfl_xor_sync(0xffffffffu, mx1, 1));
        mx1 = fmaxf(mx1, __shfl_xor_sync(0xffffffffu, mx1, 2));

        const float mn0 = fmaxf(mrow0, mx0);
        const float mn1 = fmaxf(mrow1, mx1);
        const float sc0 = __expf(mrow0 - mn0);
        const float sc1 = __expf(mrow1 - mn1);
        mrow0 = mn0; mrow1 = mn1;

        float sum0 = 0.f, sum1 = 0.f;
#pragma unroll
        for (int j = 0; j < 8; ++j) {
            S[j][0] = __expf(S[j][0] - mn0);
            S[j][1] = __expf(S[j][1] - mn0);
            S[j][2] = __expf(S[j][2] - mn1);
            S[j][3] = __expf(S[j][3] - mn1);
            sum0 += S[j][0] + S[j][1];
            sum1 += S[j][2] + S[j][3];
            ctx[j][0] *= sc0; ctx[j][1] *= sc0;
            ctx[j][2] *= sc1; ctx[j][3] *= sc1;
        }
        sum0 += __shfl_xor_sync(0xffffffffu, sum0, 1);
        sum0 += __shfl_xor_sync(0xffffffffu, sum0, 2);
        sum1 += __shfl_xor_sync(0xffffffffu, sum1, 1);
        sum1 += __shfl_xor_sync(0xffffffffu, sum1, 2);
        lrow0 = lrow0 * sc0 + sum0;
        lrow1 = lrow1 * sc1 + sum1;

        uint32_t Pf[4][4];
#pragma unroll
        for (int ks = 0; ks < 4; ++ks) {
            Pf[ks][0] = packh2(S[2 * ks][0],     S[2 * ks][1]);
            Pf[ks][1] = packh2(S[2 * ks][2],     S[2 * ks][3]);
            Pf[ks][2] = packh2(S[2 * ks + 1][0], S[2 * ks + 1][1]);
            Pf[ks][3] = packh2(S[2 * ks + 1][2], S[2 * ks + 1][3]);
        }

        // ---- ctx += P V ----
#pragma unroll
        for (int ks = 0; ks < 4; ++ks) {
#pragma unroll
            for (int nt = 0; nt < 4; ++nt) {
                uint32_t vv[4];
                const uint32_t va = (ks * 16 + arow) * FS_STR + nt * 16 + akoff;
                ldsm4t(vv, sV + va * 2);
                mma16816(ctx[nt * 2 + 0], Pf[ks], &vv[0]);
                mma16816(ctx[nt * 2 + 1], Pf[ks], &vv[2]);
            }
        }

        __syncthreads();   // all warps done with stage st before refill

        if (kt + 2 < SEQ / 64) {
            const int kn0 = (kt + 2) * 64;
#pragma unroll
            for (int i = 0; i < 2; ++i) {
                const int row = i * 32 + ldrow;
                const size_t go = (size_t)(kn0 + row) * 128 + ldseg * 16;
                const uint32_t so = row * 144 + ldseg * 16;
                cp16(sK + so, (const char*)Khg + go);
                cp16(sV + so, (const char*)Vhg + go);
            }
        }
        cp_commit();
    }

    // ---- epilogue ----
    {
        const float inv0 = 1.0f / lrow0;
        const float inv1 = 1.0f / lrow1;
        __half* c0 = Ctx + (size_t)(b * SEQ + qr0) * DMODEL + h * DHEAD;
        __half* c1 = Ctx + (size_t)(b * SEQ + qr0 + 8) * DMODEL + h * DHEAD;
#pragma unroll
        for (int j = 0; j < 8; ++j) {
            const int d = j * 8 + tg * 2;
            __half2 p0 = __floats2half2_rn(ctx[j][0] * inv0, ctx[j][1] * inv0);
            __half2 p1 = __floats2half2_rn(ctx[j][2] * inv1, ctx[j][3] * inv1);
            *(uint32_t*)(c0 + d) = *(uint32_t*)&p0;
            *(uint32_t*)(c1 + d) = *(uint32_t*)&p1;
        }
    }
}

// ---------------------------------------------------------------------------
extern "C" void kernel_launch(void* const* d_in, const int* in_sizes, int n_in,
                              void* d_out, int out_size)
{
    const float* q    = (const float*)d_in[0];
    const float* k    = (const float*)d_in[1];
    const float* v    = (const float*)d_in[2];
    const int*   mask = (const int*)  d_in[3];
    const float* Wq   = (const float*)d_in[4];
    const float* bq   = (const float*)d_in[5];
    const float* Wk   = (const float*)d_in[6];
    const float* bk   = (const float*)d_in[7];
    const float* Wv   = (const float*)d_in[8];
    const float* bv   = (const float*)d_in[9];
    const float* Wo   = (const float*)d_in[10];
    const float* bo   = (const float*)d_in[11];
    float* out = (float*)d_out;

    __half *Xq, *Xk, *Xv, *W0, *W1, *W2, *W3, *Qh, *Kh, *Vh, *Ctx;
    unsigned char* flags;
    cudaGetSymbolAddress((void**)&Xq, g_Xq);
    cudaGetSymbolAddress((void**)&Xk, g_Xk);
    cudaGetSymbolAddress((void**)&Xv, g_Xv);
    cudaGetSymbolAddress((void**)&W0, g_W0);
    cudaGetSymbolAddress((void**)&W1, g_W1);
    cudaGetSymbolAddress((void**)&W2, g_W2);
    cudaGetSymbolAddress((void**)&W3, g_W3);
    cudaGetSymbolAddress((void**)&Qh, g_Qh);
    cudaGetSymbolAddress((void**)&Kh, g_Kh);
    cudaGetSymbolAddress((void**)&Vh, g_Vh);
    cudaGetSymbolAddress((void**)&Ctx, g_Ctx);
    cudaGetSymbolAddress((void**)&flags, g_tileAll);

    cudaFuncSetAttribute(gemm_fp16<0>, cudaFuncAttributeMaxDynamicSharedMemorySize, GEMM_SMEM);
    cudaFuncSetAttribute(gemm_fp16<1>, cudaFuncAttributeMaxDynamicSharedMemorySize, GEMM_SMEM);
    cudaFuncSetAttribute(flash_mma, cudaFuncAttributeMaxDynamicSharedMemorySize, FLASH_SMEM);

    const int n4x = MROWS * DMODEL / 4;
    const int n4w = DMODEL * DMODEL / 4;

    to_half<<<dim3(n4x / 1024, 1, 3), 256>>>(q, k, v, nullptr, Xq, Xk, Xv, nullptr, n4x);
    to_half<<<dim3(n4w / 1024, 1, 4), 256>>>(Wq, Wk, Wv, Wo, W0, W1, W2, W3, n4w);
    mask_tiles<<<dim3(16, 32), 256>>>(mask, flags);

    const dim3 qkvGrid(DMODEL / CTA_N, MROWS / CTA_M, 3);
    gemm_fp16<1><<<qkvGrid, 256, GEMM_SMEM>>>(Xq, Xk, Xv, W0, W1, W2,
                                              bq, bk, bv, Qh, Kh, Vh, nullptr);

    flash_mma<<<dim3(SEQ / 128, BATCH * NHEAD), 256, FLASH_SMEM>>>(Qh, Kh, Vh, mask, flags, Ctx);

    const dim3 outGrid(DMODEL / CTA_N, MROWS / CTA_M, 1);
    gemm_fp16<0><<<outGrid, 256, GEMM_SMEM>>>(Ctx, nullptr, nullptr, W3, nullptr, nullptr,
                                              bo, nullptr, nullptr,
                                              nullptr, nullptr, nullptr, out);
}

// round 15
// speedup vs baseline: 1.5824x; 1.5824x over previous
#include <cuda_runtime.h>
#include <cuda_fp16.h>
#include <math.h>
#include <stdint.h>

#define BATCH  2
#define SEQ    2048
#define DMODEL 1024
#define NHEAD  16
#define DHEAD  64
#define MROWS  (BATCH*SEQ)   // 4096
#define KDIM   1024

// softmax in base-2 domain: scale = 0.125 * log2(e)
#define SCALE_L2E 0.18033688011112042f

// ---------------------------------------------------------------------------
// Scratch (__device__ globals; no allocation allowed)
// ---------------------------------------------------------------------------
__device__ __half g_Xq[MROWS*DMODEL];
__device__ __half g_Xk[MROWS*DMODEL];
__device__ __half g_Xv[MROWS*DMODEL];
__device__ __half g_W0[DMODEL*DMODEL];
__device__ __half g_W1[DMODEL*DMODEL];
__device__ __half g_W2[DMODEL*DMODEL];
__device__ __half g_W3[DMODEL*DMODEL];
__device__ __half g_Qh[MROWS*DMODEL];   // head-major [b][h][s][64]
__device__ __half g_Kh[MROWS*DMODEL];
__device__ __half g_Vh[MROWS*DMODEL];
__device__ __half g_Ctx[MROWS*DMODEL];  // row-major fp16 context
__device__ unsigned char g_tileAll[16*32];   // per (qtile128, ktile64) all-nonzero flag

__device__ __forceinline__ uint32_t smem_u32(const void* p) {
    uint32_t a;
    asm("{ .reg .u64 t; cvta.to.shared.u64 t, %1; cvt.u32.u64 %0, t; }" : "=r"(a) : "l"(p));
    return a;
}
__device__ __forceinline__ float fexp2(float x) {
    float y;
    asm("ex2.approx.ftz.f32 %0, %1;" : "=f"(y) : "f"(x));
    return y;
}

// ---------------------------------------------------------------------------
// fp32 -> fp16 convert, 4 float4 per thread, batched over blockIdx.z
// ---------------------------------------------------------------------------
__global__ void to_half(const float* __restrict__ s0, const float* __restrict__ s1,
                        const float* __restrict__ s2, const float* __restrict__ s3,
                        __half* __restrict__ d0, __half* __restrict__ d1,
                        __half* __restrict__ d2, __half* __restrict__ d3, int n4)
{
    const int z = blockIdx.z;
    const float* s = (z == 0) ? s0 : (z == 1) ? s1 : (z == 2) ? s2 : s3;
    __half*      d = (z == 0) ? d0 : (z == 1) ? d1 : (z == 2) ? d2 : d3;
    const int base = blockIdx.x * (blockDim.x * 4) + threadIdx.x;

    float4 x[4];
#pragma unroll
    for (int j = 0; j < 4; ++j) {
        const int idx = base + j * blockDim.x;
        if (idx < n4) x[j] = ((const float4*)s)[idx];
    }
#pragma unroll
    for (int j = 0; j < 4; ++j) {
        const int idx = base + j * blockDim.x;
        if (idx < n4) {
            __half2 a = __floats2half2_rn(x[j].x, x[j].y);
            __half2 b = __floats2half2_rn(x[j].z, x[j].w);
            ((uint2*)d)[idx] = make_uint2(*(uint32_t*)&a, *(uint32_t*)&b);
        }
    }
}

// ---------------------------------------------------------------------------
// mask tile reduction
// ---------------------------------------------------------------------------
__global__ void mask_tiles(const int* __restrict__ mask, unsigned char* __restrict__ flags)
{
    __shared__ int ok;
    const int t = threadIdx.x;
    if (t == 0) ok = 1;
    __syncthreads();
    const int r  = t >> 1;
    const int c0 = (t & 1) * 32;
    const int* p = mask + (size_t)(blockIdx.x * 128 + r) * SEQ + blockIdx.y * 64 + c0;
    int all = 1;
#pragma unroll
    for (int i = 0; i < 8; ++i) {
        int4 v = ((const int4*)p)[i];
        all &= (v.x != 0) & (v.y != 0) & (v.z != 0) & (v.w != 0);
    }
    if (!all) ok = 0;
    __syncthreads();
    if (t == 0) flags[blockIdx.x * 32 + blockIdx.y] = (unsigned char)ok;
}

// ---------------------------------------------------------------------------
// mma primitives (fp16)
// ---------------------------------------------------------------------------
__device__ __forceinline__ void cp16(uint32_t smem, const void* gmem) {
    asm volatile("cp.async.cg.shared.global [%0], [%1], 16;" :: "r"(smem), "l"(gmem));
}
__device__ __forceinline__ void cp_commit() { asm volatile("cp.async.commit_group;"); }
template<int N> __device__ __forceinline__ void cp_wait() {
    asm volatile("cp.async.wait_group %0;" :: "n"(N));
}
__device__ __forceinline__ void ldsm4(uint32_t* r, uint32_t addr) {
    asm volatile("ldmatrix.sync.aligned.m8n8.x4.shared.b16 {%0,%1,%2,%3}, [%4];"
        : "=r"(r[0]), "=r"(r[1]), "=r"(r[2]), "=r"(r[3]) : "r"(addr));
}
__device__ __forceinline__ void ldsm4t(uint32_t* r, uint32_t addr) {
    asm volatile("ldmatrix.sync.aligned.m8n8.x4.trans.shared.b16 {%0,%1,%2,%3}, [%4];"
        : "=r"(r[0]), "=r"(r[1]), "=r"(r[2]), "=r"(r[3]) : "r"(addr));
}
__device__ __forceinline__ void mma16816(float* d, const uint32_t* a, const uint32_t* b) {
    asm volatile(
        "mma.sync.aligned.m16n8k16.row.col.f32.f16.f16.f32 "
        "{%0,%1,%2,%3}, {%4,%5,%6,%7}, {%8,%9}, {%0,%1,%2,%3};"
        : "+f"(d[0]), "+f"(d[1]), "+f"(d[2]), "+f"(d[3])
        : "r"(a[0]), "r"(a[1]), "r"(a[2]), "r"(a[3]), "r"(b[0]), "r"(b[1]));
}
__device__ __forceinline__ uint32_t packh2(float lo, float hi) {
    uint32_t r;
    asm("cvt.rn.f16x2.f32 %0, %1, %2;" : "=r"(r) : "f"(hi), "f"(lo));
    return r;
}

// ---------------------------------------------------------------------------
// fp16 mma GEMM (unchanged)
// ---------------------------------------------------------------------------
#define CTA_M   128
#define CTA_N   128
#define CTA_K   64
#define STAGES  3
#define ASTR    72
#define TILE_ELE  (128 * ASTR)
#define STAGE_ELE (2 * TILE_ELE)
#define GEMM_SMEM (STAGES * STAGE_ELE * 2)

template<int HEADS_OUT>
__global__ __launch_bounds__(256, 2)
void gemm_fp16(const __half* __restrict__ A0, const __half* __restrict__ A1,
               const __half* __restrict__ A2,
               const __half* __restrict__ B0, const __half* __restrict__ B1,
               const __half* __restrict__ B2,
               const float* __restrict__ bias0, const float* __restrict__ bias1,
               const float* __restrict__ bias2,
               __half* __restrict__ H0, __half* __restrict__ H1,
               __half* __restrict__ H2, float* __restrict__ Y)
{
    extern __shared__ char smem[];
    const uint32_t sb = smem_u32(smem);
    const int t = threadIdx.x;
    const int warp = t >> 5, lane = t & 31;
    const int wm = warp >> 1, wn = warp & 1;
    const int row0 = blockIdx.y * CTA_M;
    const int col0 = blockIdx.x * CTA_N;
    const int z = blockIdx.z;

    const __half* A = (z == 0) ? A0 : (z == 1) ? A1 : A2;
    const __half* B = (z == 0) ? B0 : (z == 1) ? B1 : B2;
    const float* bias = (z == 0) ? bias0 : (z == 1) ? bias1 : bias2;
    __half* H = (z == 0) ? H0 : (z == 1) ? H1 : H2;

    const int NK = KDIM / CTA_K;   // 16

#pragma unroll
    for (int s = 0; s < STAGES - 1; ++s) {
        const uint32_t so = sb + s * STAGE_ELE * 2;
#pragma unroll
        for (int i = 0; i < 4; ++i) {
            const int id = i * 256 + t;
            const int row = id >> 3, seg = id & 7;
            const uint32_t sm = row * 144 + seg * 16;
            cp16(so + sm,
                 (const char*)A + ((size_t)(row0 + row) * KDIM + s * CTA_K) * 2 + seg * 16);
            cp16(so + TILE_ELE * 2 + sm,
                 (const char*)B + ((size_t)(col0 + row) * KDIM + s * CTA_K) * 2 + seg * 16);
        }
        cp_commit();
    }

    float acc[2][8][4];
#pragma unroll
    for (int i = 0; i < 2; ++i)
#pragma unroll
        for (int j = 0; j < 8; ++j)
#pragma unroll
            for (int c = 0; c < 4; ++c) acc[i][j][c] = 0.f;

    const int g = lane >> 3, r = lane & 7;
    const int aRow = wm * 32 + (g & 1) * 8 + r;
    const int aK   = (g >> 1) * 8;
    const int bRow = wn * 64 + (g >> 1) * 8 + r;
    const int bK   = (g & 1) * 8;

    for (int ks = 0; ks < NK; ++ks) {
        cp_wait<1>();
        __syncthreads();

        const int kn = ks + STAGES - 1;
        if (kn < NK) {
            const uint32_t so = sb + (kn % STAGES) * STAGE_ELE * 2;
#pragma unroll
            for (int i = 0; i < 4; ++i) {
                const int id = i * 256 + t;
                const int row = id >> 3, seg = id & 7;
                const uint32_t sm = row * 144 + seg * 16;
                cp16(so + sm,
                     (const char*)A + ((size_t)(row0 + row) * KDIM + kn * CTA_K) * 2 + seg * 16);
                cp16(so + TILE_ELE * 2 + sm,
                     (const char*)B + ((size_t)(col0 + row) * KDIM + kn * CTA_K) * 2 + seg * 16);
            }
        }
        cp_commit();

        const uint32_t sAst = sb + (ks % STAGES) * STAGE_ELE * 2;
        const uint32_t sBst = sAst + TILE_ELE * 2;

#pragma unroll
        for (int kk = 0; kk < 4; ++kk) {
            uint32_t af[2][4], bf[4][4];
#pragma unroll
            for (int mt = 0; mt < 2; ++mt)
                ldsm4(af[mt], sAst + ((aRow + mt * 16) * ASTR + kk * 16 + aK) * 2);
#pragma unroll
            for (int nn = 0; nn < 4; ++nn)
                ldsm4(bf[nn], sBst + ((bRow + nn * 16) * ASTR + kk * 16 + bK) * 2);
#pragma unroll
            for (int mt = 0; mt < 2; ++mt)
#pragma unroll
                for (int nn = 0; nn < 4; ++nn) {
                    mma16816(acc[mt][nn * 2 + 0], af[mt], &bf[nn][0]);
                    mma16816(acc[mt][nn * 2 + 1], af[mt], &bf[nn][2]);
                }
        }
    }

    const int mBase = row0 + wm * 32 + (lane >> 2);
    const int nBase = col0 + wn * 64 + (lane & 3) * 2;
#pragma unroll
    for (int mt = 0; mt < 2; ++mt) {
#pragma unroll
        for (int nt = 0; nt < 8; ++nt) {
            const int gcol = nBase + nt * 8;
            const float2 bb = *(const float2*)&bias[gcol];
            const float v0a = acc[mt][nt][0] + bb.x;
            const float v0b = acc[mt][nt][1] + bb.y;
            const float v1a = acc[mt][nt][2] + bb.x;
            const float v1b = acc[mt][nt][3] + bb.y;
            const int grow0 = mBase + mt * 16;
            const int grow1 = grow0 + 8;
            if (HEADS_OUT) {
                const int h = gcol >> 6, c = gcol & 63;
                const int b0 = grow0 >> 11, s0 = grow0 & 2047;
                const int b1 = grow1 >> 11, s1 = grow1 & 2047;
                const size_t d0 = ((size_t)(b0 * 16 + h) * 2048 + s0) * 64 + c;
                const size_t d1 = ((size_t)(b1 * 16 + h) * 2048 + s1) * 64 + c;
                __half2 p0 = __floats2half2_rn(v0a, v0b);
                __half2 p1 = __floats2half2_rn(v1a, v1b);
                *(uint32_t*)(H + d0) = *(uint32_t*)&p0;
                *(uint32_t*)(H + d1) = *(uint32_t*)&p1;
            } else {
                *(float2*)&Y[(size_t)grow0 * DMODEL + gcol] = make_float2(v0a, v0b);
                *(float2*)&Y[(size_t)grow1 * DMODEL + gcol] = make_float2(v1a, v1b);
            }
        }
    }
}

// ---------------------------------------------------------------------------
// Flash attention, fp16 HMMA: 256 threads / 8 warps, 16 Q-rows per warp.
// Softmax in base-2 domain (folded 0.125*log2e scale, raw ex2.approx).
// ---------------------------------------------------------------------------
#define FS_STR   72
#define QELE     (128 * FS_STR)       // 9216
#define KVELE    (64 * FS_STR)        // 4608
#define FLASH_SMEM ((QELE + 4 * KVELE) * 2)   // 55296 bytes

__global__ __launch_bounds__(256, 2)
void flash_mma(const __half* __restrict__ Qg, const __half* __restrict__ Kg,
               const __half* __restrict__ Vg, const int* __restrict__ mask,
               const unsigned char* __restrict__ tileAll, __half* __restrict__ Ctx)
{
    extern __shared__ char smem[];
    const uint32_t sb = smem_u32(smem);
    const int t = threadIdx.x;
    const int warp = t >> 5, lane = t & 31;
    const int grp = lane >> 2, tg = lane & 3;
    const int bh = blockIdx.y;
    const int b  = bh >> 4, h = bh & 15;
    const int q0 = blockIdx.x * 128;

    const size_t headOff = (size_t)bh * SEQ * DHEAD;
    const __half* Qhg = Qg + headOff;
    const __half* Khg = Kg + headOff;
    const __half* Vhg = Vg + headOff;

    const int ldrow = t >> 3, ldseg = t & 7;

    // prologue: Q (4 segs/thread) + KV(0) as group0; KV(1) as group1
#pragma unroll
    for (int i = 0; i < 4; ++i) {
        const int id = i * 256 + t;
        const int row = id >> 3, seg = id & 7;
        cp16(sb + row * 144 + seg * 16,
             (const char*)Qhg + (size_t)(q0 + row) * 128 + seg * 16);
    }
#pragma unroll
    for (int i = 0; i < 2; ++i) {
        const int row = i * 32 + ldrow;
        const size_t go = (size_t)row * 128 + ldseg * 16;
        const uint32_t so = row * 144 + ldseg * 16;
        cp16(sb + QELE * 2 + so, (const char*)Khg + go);
        cp16(sb + (QELE + KVELE) * 2 + so, (const char*)Vhg + go);
    }
    cp_commit();
#pragma unroll
    for (int i = 0; i < 2; ++i) {
        const int row = i * 32 + ldrow;
        const size_t go = (size_t)(64 + row) * 128 + ldseg * 16;
        const uint32_t so = row * 144 + ldseg * 16;
        cp16(sb + (QELE + 2 * KVELE) * 2 + so, (const char*)Khg + go);
        cp16(sb + (QELE + 3 * KVELE) * 2 + so, (const char*)Vhg + go);
    }
    cp_commit();

    const int g2 = lane >> 3, r8 = lane & 7;
    const int arow = (g2 & 1) * 8 + r8;
    const int akoff = (lane >> 4) * 8;
    const int brow = (lane >> 4) * 8 + r8;
    const int bkoff = (g2 & 1) * 8;

    float ctx[8][4];
    float mrow0 = -INFINITY, mrow1 = -INFINITY, lrow0 = 0.f, lrow1 = 0.f;
#pragma unroll
    for (int j = 0; j < 8; ++j)
#pragma unroll
        for (int c = 0; c < 4; ++c) ctx[j][c] = 0.f;

    const int qr0 = q0 + warp * 16 + grp;
    const unsigned char* flagRow = tileAll + blockIdx.x * 32;

    for (int kt = 0; kt < SEQ / 64; ++kt) {
        const int k0 = kt * 64;
        const int st = kt & 1;
        const uint32_t sK = sb + (QELE + 2 * st * KVELE) * 2;
        const uint32_t sV = sK + KVELE * 2;

        cp_wait<1>();
        __syncthreads();

        const int allOnes = flagRow[kt];

        // ---- S = Q K^T ----
        float S[8][4];
#pragma unroll
        for (int j = 0; j < 8; ++j)
#pragma unroll
            for (int c = 0; c < 4; ++c) S[j][c] = 0.f;

#pragma unroll
        for (int kk = 0; kk < 4; ++kk) {
            uint32_t aQ[4];
            const uint32_t qa = (warp * 16 + arow) * FS_STR + kk * 16 + akoff;
            ldsm4(aQ, sb + qa * 2);
#pragma unroll
            for (int nt = 0; nt < 4; ++nt) {
                uint32_t bK4[4];
                const uint32_t ka = (nt * 16 + brow) * FS_STR + kk * 16 + bkoff;
                ldsm4(bK4, sK + ka * 2);
                mma16816(S[nt * 2 + 0], aQ, &bK4[0]);
                mma16816(S[nt * 2 + 1], aQ, &bK4[2]);
            }
        }

        // ---- mask/scale (base-2 domain) + online softmax + pack P ----
        const int row0 = qr0;
        const int row1 = qr0 + 8;
        float mx0 = -INFINITY, mx1 = -INFINITY;
        if (allOnes) {
#pragma unroll
            for (int j = 0; j < 8; ++j) {
                S[j][0] *= SCALE_L2E; S[j][1] *= SCALE_L2E;
                S[j][2] *= SCALE_L2E; S[j][3] *= SCALE_L2E;
                mx0 = fmaxf(mx0, fmaxf(S[j][0], S[j][1]));
                mx1 = fmaxf(mx1, fmaxf(S[j][2], S[j][3]));
            }
        } else {
#pragma unroll
            for (int j = 0; j < 8; ++j) {
                const int kcol = k0 + j * 8 + tg * 2;
                const int2 mv0 = *(const int2*)&mask[(size_t)row0 * SEQ + kcol];
                const int2 mv1 = *(const int2*)&mask[(size_t)row1 * SEQ + kcol];
                S[j][0] = mv0.x ? S[j][0] * SCALE_L2E : -1e9f;
                S[j][1] = mv0.y ? S[j][1] * SCALE_L2E : -1e9f;
                S[j][2] = mv1.x ? S[j][2] * SCALE_L2E : -1e9f;
                S[j][3] = mv1.y ? S[j][3] * SCALE_L2E : -1e9f;
                mx0 = fmaxf(mx0, fmaxf(S[j][0], S[j][1]));
                mx1 = fmaxf(mx1, fmaxf(S[j][2], S[j][3]));
            }
        }
        mx0 = fmaxf(mx0, __shfl_xor_sync(0xffffffffu, mx0, 1));
        mx0 = fmaxf(mx0, __shfl_xor_sync(0xffffffffu, mx0, 2));
        mx1 = fmaxf(mx1, __shfl_xor_sync(0xffffffffu, mx1, 1));
        mx1 = fmaxf(mx1, __shfl_xor_sync(0xffffffffu, mx1, 2));

        const float mn0 = fmaxf(mrow0, mx0);
        const float mn1 = fmaxf(mrow1, mx1);
        const float sc0 = fexp2(mrow0 - mn0);
        const float sc1 = fexp2(mrow1 - mn1);
        mrow0 = mn0; mrow1 = mn1;

        float sum0 = 0.f, sum1 = 0.f;
#pragma unroll
        for (int j = 0; j < 8; ++j) {
            S[j][0] = fexp2(S[j][0] - mn0);
            S[j][1] = fexp2(S[j][1] - mn0);
            S[j][2] = fexp2(S[j][2] - mn1);
            S[j][3] = fexp2(S[j][3] - mn1);
            sum0 += S[j][0] + S[j][1];
            sum1 += S[j][2] + S[j][3];
            ctx[j][0] *= sc0; ctx[j][1] *= sc0;
            ctx[j][2] *= sc1; ctx[j][3] *= sc1;
        }
        sum0 += __shfl_xor_sync(0xffffffffu, sum0, 1);
        sum0 += __shfl_xor_sync(0xffffffffu, sum0, 2);
        sum1 += __shfl_xor_sync(0xffffffffu, sum1, 1);
        sum1 += __shfl_xor_sync(0xffffffffu, sum1, 2);
        lrow0 = lrow0 * sc0 + sum0;
        lrow1 = lrow1 * sc1 + sum1;

        uint32_t Pf[4][4];
#pragma unroll
        for (int ks = 0; ks < 4; ++ks) {
            Pf[ks][0] = packh2(S[2 * ks][0],     S[2 * ks][1]);
            Pf[ks][1] = packh2(S[2 * ks][2],     S[2 * ks][3]);
            Pf[ks][2] = packh2(S[2 * ks + 1][0], S[2 * ks + 1][1]);
            Pf[ks][3] = packh2(S[2 * ks + 1][2], S[2 * ks + 1][3]);
        }

        // ---- ctx += P V ----
#pragma unroll
        for (int ks = 0; ks < 4; ++ks) {
#pragma unroll
            for (int nt = 0; nt < 4; ++nt) {
                uint32_t vv[4];
                const uint32_t va = (ks * 16 + arow) * FS_STR + nt * 16 + akoff;
                ldsm4t(vv, sV + va * 2);
                mma16816(ctx[nt * 2 + 0], Pf[ks], &vv[0]);
                mma16816(ctx[nt * 2 + 1], Pf[ks], &vv[2]);
            }
        }

        __syncthreads();

        if (kt + 2 < SEQ / 64) {
            const int kn0 = (kt + 2) * 64;
#pragma unroll
            for (int i = 0; i < 2; ++i) {
                const int row = i * 32 + ldrow;
                const size_t go = (size_t)(kn0 + row) * 128 + ldseg * 16;
                const uint32_t so = row * 144 + ldseg * 16;
                cp16(sK + so, (const char*)Khg + go);
                cp16(sV + so, (const char*)Vhg + go);
            }
        }
        cp_commit();
    }

    // ---- epilogue ----
    {
        const float inv0 = 1.0f / lrow0;
        const float inv1 = 1.0f / lrow1;
        __half* c0 = Ctx + (size_t)(b * SEQ + qr0) * DMODEL + h * DHEAD;
        __half* c1 = Ctx + (size_t)(b * SEQ + qr0 + 8) * DMODEL + h * DHEAD;
#pragma unroll
        for (int j = 0; j < 8; ++j) {
            const int d = j * 8 + tg * 2;
            __half2 p0 = __floats2half2_rn(ctx[j][0] * inv0, ctx[j][1] * inv0);
            __half2 p1 = __floats2half2_rn(ctx[j][2] * inv1, ctx[j][3] * inv1);
            *(uint32_t*)(c0 + d) = *(uint32_t*)&p0;
            *(uint32_t*)(c1 + d) = *(uint32_t*)&p1;
        }
    }
}

// ---------------------------------------------------------------------------
extern "C" void kernel_launch(void* const* d_in, const int* in_sizes, int n_in,
                              void* d_out, int out_size)
{
    const float* q    = (const float*)d_in[0];
    const float* k    = (const float*)d_in[1];
    const float* v    = (const float*)d_in[2];
    const int*   mask = (const int*)  d_in[3];
    const float* Wq   = (const float*)d_in[4];
    const float* bq   = (const float*)d_in[5];
    const float* Wk   = (const float*)d_in[6];
    const float* bk   = (const float*)d_in[7];
    const float* Wv   = (const float*)d_in[8];
    const float* bv   = (const float*)d_in[9];
    const float* Wo   = (const float*)d_in[10];
    const float* bo   = (const float*)d_in[11];
    float* out = (float*)d_out;

    __half *Xq, *Xk, *Xv, *W0, *W1, *W2, *W3, *Qh, *Kh, *Vh, *Ctx;
    unsigned char* flags;
    cudaGetSymbolAddress((void**)&Xq, g_Xq);
    cudaGetSymbolAddress((void**)&Xk, g_Xk);
    cudaGetSymbolAddress((void**)&Xv, g_Xv);
    cudaGetSymbolAddress((void**)&W0, g_W0);
    cudaGetSymbolAddress((void**)&W1, g_W1);
    cudaGetSymbolAddress((void**)&W2, g_W2);
    cudaGetSymbolAddress((void**)&W3, g_W3);
    cudaGetSymbolAddress((void**)&Qh, g_Qh);
    cudaGetSymbolAddress((void**)&Kh, g_Kh);
    cudaGetSymbolAddress((void**)&Vh, g_Vh);
    cudaGetSymbolAddress((void**)&Ctx, g_Ctx);
    cudaGetSymbolAddress((void**)&flags, g_tileAll);

    cudaFuncSetAttribute(gemm_fp16<0>, cudaFuncAttributeMaxDynamicSharedMemorySize, GEMM_SMEM);
    cudaFuncSetAttribute(gemm_fp16<1>, cudaFuncAttributeMaxDynamicSharedMemorySize, GEMM_SMEM);
    cudaFuncSetAttribute(flash_mma, cudaFuncAttributeMaxDynamicSharedMemorySize, FLASH_SMEM);

    const int n4x = MROWS * DMODEL / 4;
    const int n4w = DMODEL * DMODEL / 4;

    to_half<<<dim3(n4x / 1024, 1, 3), 256>>>(q, k, v, nullptr, Xq, Xk, Xv, nullptr, n4x);
    to_half<<<dim3(n4w / 1024, 1, 4), 256>>>(Wq, Wk, Wv, Wo, W0, W1, W2, W3, n4w);
    mask_tiles<<<dim3(16, 32), 256>>>(mask, flags);

    const dim3 qkvGrid(DMODEL / CTA_N, MROWS / CTA_M, 3);
    gemm_fp16<1><<<qkvGrid, 256, GEMM_SMEM>>>(Xq, Xk, Xv, W0, W1, W2,
                                              bq, bk, bv, Qh, Kh, Vh, nullptr);

    flash_mma<<<dim3(SEQ / 128, BATCH * NHEAD), 256, FLASH_SMEM>>>(Qh, Kh, Vh, mask, flags, Ctx);

    const dim3 outGrid(DMODEL / CTA_N, MROWS / CTA_M, 1);
    gemm_fp16<0><<<outGrid, 256, GEMM_SMEM>>>(Ctx, nullptr, nullptr, W3, nullptr, nullptr,
                                              bo, nullptr, nullptr,
                                              nullptr, nullptr, nullptr, out);
}